// round 1
// baseline (speedup 1.0000x reference)
#include <cuda_runtime.h>
#include <cuda_bf16.h>
#include <cstdint>

// Problem constants
#define NV 128   // vocab
#define NE 64    // embed
#define NH 128   // hidden
#define NC 12    // classes
#define NB 2048  // batch
#define NT 256   // timesteps
#define MB 16    // batch tile per block
#define SROW 136 // s0 smem row stride in bf16 elements (272B: conflict-free for ldmatrix)

// Scratch (device globals: no allocation allowed)
__device__ float g_Q[NV * NH];
__device__ __align__(16) unsigned short g_W1hi[NH * NH];
__device__ __align__(16) unsigned short g_W1lo[NH * NH];

// ---------------------------------------------------------------------------
// Prep kernel 1: Q[v,h] = ((emb[v,:]@W_in.T + b_in) @ W_lif0.T + b_lif0)[h]
// grid = NV blocks, NH threads
// ---------------------------------------------------------------------------
__global__ void prep_q_kernel(const float* __restrict__ emb,
                              const float* __restrict__ W_in,
                              const float* __restrict__ b_in,
                              const float* __restrict__ W_lif,
                              const float* __restrict__ b_lif) {
    __shared__ float es[NE];
    __shared__ float Ps[NH];
    int v = blockIdx.x;
    int h = threadIdx.x;
    if (h < NE) es[h] = emb[v * NE + h];
    __syncthreads();
    float p = 0.f;
#pragma unroll 8
    for (int e = 0; e < NE; e++) p += es[e] * W_in[h * NE + e];
    Ps[h] = p + b_in[h];
    __syncthreads();
    float q = 0.f;
#pragma unroll 8
    for (int i = 0; i < NH; i++) q += Ps[i] * W_lif[h * NH + i];
    g_Q[v * NH + h] = q + b_lif[h];
}

// ---------------------------------------------------------------------------
// Prep kernel 2: split W_lif[1] into bf16 hi + bf16 lo (exact 2-term split)
// ---------------------------------------------------------------------------
__global__ void prep_w_kernel(const float* __restrict__ W_lif) {
    int i = blockIdx.x * blockDim.x + threadIdx.x;
    if (i < NH * NH) {
        float w = W_lif[NH * NH + i];  // layer 1
        __nv_bfloat16 hi = __float2bfloat16(w);
        float rem = w - __bfloat162float(hi);
        __nv_bfloat16 lo = __float2bfloat16(rem);
        g_W1hi[i] = *reinterpret_cast<unsigned short*>(&hi);
        g_W1lo[i] = *reinterpret_cast<unsigned short*>(&lo);
    }
}

// ---------------------------------------------------------------------------
// mma.sync m16n8k16 bf16 -> fp32 accumulate
// ---------------------------------------------------------------------------
__device__ __forceinline__ void mma_bf16(float c[4], uint32_t a0, uint32_t a1,
                                         uint32_t a2, uint32_t a3,
                                         uint32_t b0, uint32_t b1) {
    asm volatile(
        "mma.sync.aligned.m16n8k16.row.col.f32.bf16.bf16.f32 "
        "{%0,%1,%2,%3},{%4,%5,%6,%7},{%8,%9},{%0,%1,%2,%3};"
        : "+f"(c[0]), "+f"(c[1]), "+f"(c[2]), "+f"(c[3])
        : "r"(a0), "r"(a1), "r"(a2), "r"(a3), "r"(b0), "r"(b1));
}

// smem layout (dynamic):
//   [0      , 65536 )  Q table        (128*128 f32)
//   [65536  , 81920 )  ids            (16*256  i32)
//   [81920  , 88064 )  W_cls          (12*128  f32)
//   [88064  , 92416 )  s0 tile        (16*136  bf16)
//   [92416  , 100608)  acc spill      (16*128  f32)
#define SM_BYTES 100608

__global__ __launch_bounds__(256, 1) void snn_main_kernel(
    const int* __restrict__ ids, const float* __restrict__ b_lif,
    const float* __restrict__ W_cls, const float* __restrict__ b_cls,
    float* __restrict__ out) {
    extern __shared__ char smem[];
    float* Qs = (float*)smem;
    int* idss = (int*)(smem + 65536);
    float* wclss = (float*)(smem + 81920);
    unsigned short* s0s = (unsigned short*)(smem + 88064);
    float* accs = (float*)(smem + 92416);

    const int tid = threadIdx.x;
    const int lane = tid & 31;
    const int warp = tid >> 5;
    const int g = lane >> 2;    // group id (row within fragment)
    const int tig = lane & 3;   // thread in group
    const int b0 = blockIdx.x * MB;

    // ---- cooperative smem fills ----
    {
        const float4* src = (const float4*)g_Q;
        float4* dst = (float4*)Qs;
#pragma unroll
        for (int i = tid; i < NV * NH / 4; i += 256) dst[i] = src[i];
    }
    {
        const int4* src = (const int4*)(ids + b0 * NT);
        int4* dst = (int4*)idss;
#pragma unroll
        for (int i = tid; i < MB * NT / 4; i += 256) dst[i] = src[i];
    }
    {
        const float4* src = (const float4*)W_cls;
        float4* dst = (float4*)wclss;
        for (int i = tid; i < NC * NH / 4; i += 256) dst[i] = src[i];
    }

    // ---- register-resident B fragments: W1 hi/lo, [kt][nt][reg] ----
    const int nb = warp * 16;  // this warp's 16 output-h slice
    uint32_t Bhi[8][2][2], Blo[8][2][2];
#pragma unroll
    for (int kt = 0; kt < 8; kt++) {
#pragma unroll
        for (int nt = 0; nt < 2; nt++) {
            int n = nb + nt * 8 + g;
            int k = kt * 16 + tig * 2;
            Bhi[kt][nt][0] = *(const uint32_t*)(g_W1hi + n * NH + k);
            Bhi[kt][nt][1] = *(const uint32_t*)(g_W1hi + n * NH + k + 8);
            Blo[kt][nt][0] = *(const uint32_t*)(g_W1lo + n * NH + k);
            Blo[kt][nt][1] = *(const uint32_t*)(g_W1lo + n * NH + k + 8);
        }
    }

    // bias (layer 1) at this thread's C-fragment columns
    float bias[2][2];
#pragma unroll
    for (int nt = 0; nt < 2; nt++) {
        bias[nt][0] = b_lif[NH + nb + nt * 8 + tig * 2];
        bias[nt][1] = b_lif[NH + nb + nt * 8 + tig * 2 + 1];
    }

    // layer-0 state: thread owns (hp, 8 consecutive b)
    const int hp = tid & (NH - 1);
    const int bh = (tid >> 7) * 8;
    float v0[8];
#pragma unroll
    for (int j = 0; j < 8; j++) v0[j] = 0.f;

    // layer-1 state in C-fragment layout
    float v1[2][4], accr[2][4];
#pragma unroll
    for (int nt = 0; nt < 2; nt++)
#pragma unroll
        for (int r = 0; r < 4; r++) { v1[nt][r] = 0.f; accr[nt][r] = 0.f; }

    // ldmatrix lane address: row = lane&15, col8 = (lane>=16)
    const int arow = lane & 15;
    const int acol = (lane >= 16) ? 8 : 0;
    const uint32_t abase =
        (uint32_t)__cvta_generic_to_shared(s0s + arow * SROW + acol);

    __syncthreads();

    // =================== time loop ===================
    for (int t = 0; t < NT; t++) {
        // ---- layer 0: membrane update + spike -> s0 tile (bf16 {0,1}) ----
#pragma unroll
        for (int j = 0; j < 8; j++) {
            int b = bh + j;
            int id = idss[b * NT + t];
            float q = Qs[id * NH + hp];
            float v = 0.8f * v0[j] + 0.2f * q;
            bool s = (v >= 1.0f);
            v0[j] = s ? 0.f : v;
            s0s[b * SROW + hp] = s ? (unsigned short)0x3F80 : (unsigned short)0;
        }
        __syncthreads();

        // ---- layer 1 drive: [16 x 128] = s0 @ W1^T via mma (hi + lo) ----
        float c[2][4];
#pragma unroll
        for (int nt = 0; nt < 2; nt++)
#pragma unroll
            for (int r = 0; r < 4; r++) c[nt][r] = 0.f;

#pragma unroll
        for (int kt = 0; kt < 8; kt++) {
            uint32_t a0, a1, a2, a3;
            uint32_t ad = abase + kt * 32;  // 16 bf16 = 32B per k-tile
            asm volatile(
                "ldmatrix.sync.aligned.m8n8.x4.shared.b16 {%0,%1,%2,%3},[%4];"
                : "=r"(a0), "=r"(a1), "=r"(a2), "=r"(a3)
                : "r"(ad));
#pragma unroll
            for (int nt = 0; nt < 2; nt++) {
                mma_bf16(c[nt], a0, a1, a2, a3, Bhi[kt][nt][0], Bhi[kt][nt][1]);
                mma_bf16(c[nt], a0, a1, a2, a3, Blo[kt][nt][0], Blo[kt][nt][1]);
            }
        }
        __syncthreads();  // protect s0s before next step's writes

        // ---- layer-1 membrane/spike/reset + spike accumulation ----
#pragma unroll
        for (int nt = 0; nt < 2; nt++)
#pragma unroll
            for (int r = 0; r < 4; r++) {
                float vv = 0.8f * v1[nt][r] + 0.2f * (c[nt][r] + bias[nt][r & 1]);
                bool s = (vv >= 1.0f);
                accr[nt][r] += s ? 1.f : 0.f;
                v1[nt][r] = s ? 0.f : vv;
            }
    }

    // =================== epilogue: classifier ===================
#pragma unroll
    for (int nt = 0; nt < 2; nt++)
#pragma unroll
        for (int r = 0; r < 4; r++) {
            int bl = (r < 2) ? g : (g + 8);
            int col = nb + nt * 8 + tig * 2 + (r & 1);
            accs[bl * NH + col] = accr[nt][r];
        }
    __syncthreads();

    if (tid < MB * NC) {
        int bl = tid / NC;
        int cc = tid % NC;
        float sum = 0.f;
#pragma unroll 8
        for (int h = 0; h < NH; h++) sum += accs[bl * NH + h] * wclss[cc * NH + h];
        out[(b0 + bl) * NC + cc] = sum * (1.0f / NT) + b_cls[cc];
    }
}

// ---------------------------------------------------------------------------
// Host launcher (graph-capturable: kernel launches only)
// Input order: ids, emb, W_in, b_in, W_lif, b_lif, W_rec(unused), W_cls, b_cls
// ---------------------------------------------------------------------------
extern "C" void kernel_launch(void* const* d_in, const int* in_sizes, int n_in,
                              void* d_out, int out_size) {
    const int* ids = (const int*)d_in[0];
    const float* emb = (const float*)d_in[1];
    const float* W_in = (const float*)d_in[2];
    const float* b_in = (const float*)d_in[3];
    const float* W_lif = (const float*)d_in[4];
    const float* b_lif = (const float*)d_in[5];
    const float* W_cls = (const float*)d_in[7];
    const float* b_cls = (const float*)d_in[8];
    float* out = (float*)d_out;

    cudaFuncSetAttribute(snn_main_kernel,
                         cudaFuncAttributeMaxDynamicSharedMemorySize, SM_BYTES);

    prep_q_kernel<<<NV, NH>>>(emb, W_in, b_in, W_lif, b_lif);
    prep_w_kernel<<<64, 256>>>(W_lif);
    snn_main_kernel<<<NB / MB, 256, SM_BYTES>>>(ids, b_lif, W_cls, b_cls, out);
}

// round 2
// speedup vs baseline: 1.0234x; 1.0234x over previous
#include <cuda_runtime.h>
#include <cuda_bf16.h>
#include <cstdint>

// Problem constants
#define NV 128   // vocab
#define NE 64    // embed
#define NH 128   // hidden
#define NC 12    // classes
#define NB 2048  // batch
#define NT 256   // timesteps
#define MB 16    // batch tile per block
#define SROW 136 // s0 smem row stride in bf16 elements

// Scratch (device globals: no allocation allowed)
__device__ float g_P[NV * NH];
__device__ float g_Q[NV * NH];
__device__ __align__(16) unsigned short g_W1hi[NH * NH];
__device__ __align__(16) unsigned short g_W1lo[NH * NH];

// ---------------------------------------------------------------------------
// Prep kernel 1: P[v,h] = emb[v,:]@W_in[h,:] + b_in[h]
// 64 blocks x 256 threads, one output element per thread, W_in staged in
// padded smem (stride 65 floats -> conflict-free for the h-strided read).
// ---------------------------------------------------------------------------
__global__ __launch_bounds__(256) void prep_p_kernel(
    const float* __restrict__ emb, const float* __restrict__ W_in,
    const float* __restrict__ b_in) {
    __shared__ float wsh[NH * 65];  // W_in padded
    __shared__ float esh[2 * NE];
    const int tid = threadIdx.x;
    // stage W_in [128 x 64]
    for (int i = tid; i < NH * NE; i += 256) {
        int r = i >> 6, c = i & 63;
        wsh[r * 65 + c] = W_in[i];
    }
    // stage this block's two emb rows
    const int vbase = blockIdx.x * 2;
    for (int i = tid; i < 2 * NE; i += 256) esh[i] = emb[vbase * NE + i];
    __syncthreads();

    const int half = tid >> 7;          // which v of the pair
    const int h = tid & 127;
    float a0 = 0.f, a1 = 0.f, a2 = 0.f, a3 = 0.f;
#pragma unroll
    for (int e = 0; e < NE; e += 4) {
        a0 += esh[half * NE + e + 0] * wsh[h * 65 + e + 0];
        a1 += esh[half * NE + e + 1] * wsh[h * 65 + e + 1];
        a2 += esh[half * NE + e + 2] * wsh[h * 65 + e + 2];
        a3 += esh[half * NE + e + 3] * wsh[h * 65 + e + 3];
    }
    g_P[(vbase + half) * NH + h] = (a0 + a1) + (a2 + a3) + b_in[h];
}

// ---------------------------------------------------------------------------
// Prep kernel 2: Q[v,h] = P[v,:]@W_lif0[h,:] + b_lif0[h]
// Also performs the W_lif1 bf16 hi/lo split (grid covers exactly NH*NH).
// ---------------------------------------------------------------------------
__global__ __launch_bounds__(256) void prep_q2_kernel(
    const float* __restrict__ W_lif, const float* __restrict__ b_lif) {
    extern __shared__ float dsm[];
    float* wsh = dsm;                 // 128 x 129 padded (66048 B)
    float* psh = dsm + NH * 129;      // 2 x 128
    const int tid = threadIdx.x;
    const int gid = blockIdx.x * 256 + tid;

    // W1 split (one element per thread across the whole grid)
    {
        float w = W_lif[NH * NH + gid];  // layer 1
        __nv_bfloat16 hi = __float2bfloat16(w);
        float rem = w - __bfloat162float(hi);
        __nv_bfloat16 lo = __float2bfloat16(rem);
        g_W1hi[gid] = *reinterpret_cast<unsigned short*>(&hi);
        g_W1lo[gid] = *reinterpret_cast<unsigned short*>(&lo);
    }

    // stage W_lif0 [128 x 128] padded
    for (int i = tid; i < NH * NH; i += 256) {
        int r = i >> 7, c = i & 127;
        wsh[r * 129 + c] = W_lif[i];
    }
    const int vbase = blockIdx.x * 2;
    for (int i = tid; i < 2 * NH; i += 256) psh[i] = g_P[vbase * NH + i];
    __syncthreads();

    const int half = tid >> 7;
    const int h = tid & 127;
    float a0 = 0.f, a1 = 0.f, a2 = 0.f, a3 = 0.f;
#pragma unroll 8
    for (int i = 0; i < NH; i += 4) {
        a0 += psh[half * NH + i + 0] * wsh[h * 129 + i + 0];
        a1 += psh[half * NH + i + 1] * wsh[h * 129 + i + 1];
        a2 += psh[half * NH + i + 2] * wsh[h * 129 + i + 2];
        a3 += psh[half * NH + i + 3] * wsh[h * 129 + i + 3];
    }
    g_Q[(vbase + half) * NH + h] = (a0 + a1) + (a2 + a3) + b_lif[h];
}

// ---------------------------------------------------------------------------
// mma.sync m16n8k16 bf16 -> fp32 accumulate
// ---------------------------------------------------------------------------
__device__ __forceinline__ void mma_bf16(float c[4], uint32_t a0, uint32_t a1,
                                         uint32_t a2, uint32_t a3,
                                         uint32_t b0, uint32_t b1) {
    asm volatile(
        "mma.sync.aligned.m16n8k16.row.col.f32.bf16.bf16.f32 "
        "{%0,%1,%2,%3},{%4,%5,%6,%7},{%8,%9},{%0,%1,%2,%3};"
        : "+f"(c[0]), "+f"(c[1]), "+f"(c[2]), "+f"(c[3])
        : "r"(a0), "r"(a1), "r"(a2), "r"(a3), "r"(b0), "r"(b1));
}

// smem layout (dynamic):
//   [0      , 65536 )  Q table        (128*128 f32)
//   [65536  , 81920 )  ids            (16*256  i32)
//   [81920  , 88064 )  W_cls          (12*128  f32)
//   [88064  , 96768 )  s0 tile x2     (2 * 16*136 bf16)
//   [96768  , 104960)  acc spill      (16*128  f32)
#define SM_BYTES 104960

__global__ __launch_bounds__(256, 1) void snn_main_kernel(
    const int* __restrict__ ids, const float* __restrict__ b_lif,
    const float* __restrict__ W_cls, const float* __restrict__ b_cls,
    float* __restrict__ out) {
    extern __shared__ char smem[];
    float* Qs = (float*)smem;
    int* idss = (int*)(smem + 65536);
    float* wclss = (float*)(smem + 81920);
    unsigned short* s0s = (unsigned short*)(smem + 88064);  // [2][16][SROW]
    float* accs = (float*)(smem + 96768);

    const int tid = threadIdx.x;
    const int lane = tid & 31;
    const int warp = tid >> 5;
    const int g = lane >> 2;    // group id (row within fragment)
    const int tig = lane & 3;   // thread in group
    const int b0 = blockIdx.x * MB;

    // ---- cooperative smem fills ----
    {
        const float4* src = (const float4*)g_Q;
        float4* dst = (float4*)Qs;
#pragma unroll
        for (int i = tid; i < NV * NH / 4; i += 256) dst[i] = src[i];
    }
    {
        const int4* src = (const int4*)(ids + b0 * NT);
        int4* dst = (int4*)idss;
#pragma unroll
        for (int i = tid; i < MB * NT / 4; i += 256) dst[i] = src[i];
    }
    {
        const float4* src = (const float4*)W_cls;
        float4* dst = (float4*)wclss;
        for (int i = tid; i < NC * NH / 4; i += 256) dst[i] = src[i];
    }

    // ---- register-resident B fragments: W1 hi/lo, [kt][nt][reg] ----
    const int nb = warp * 16;  // this warp's 16 output-h slice
    uint32_t Bhi[8][2][2], Blo[8][2][2];
#pragma unroll
    for (int kt = 0; kt < 8; kt++) {
#pragma unroll
        for (int nt = 0; nt < 2; nt++) {
            int n = nb + nt * 8 + g;
            int k = kt * 16 + tig * 2;
            Bhi[kt][nt][0] = *(const uint32_t*)(g_W1hi + n * NH + k);
            Bhi[kt][nt][1] = *(const uint32_t*)(g_W1hi + n * NH + k + 8);
            Blo[kt][nt][0] = *(const uint32_t*)(g_W1lo + n * NH + k);
            Blo[kt][nt][1] = *(const uint32_t*)(g_W1lo + n * NH + k + 8);
        }
    }

    // bias (layer 1) at this thread's C-fragment columns
    float bias[2][2];
#pragma unroll
    for (int nt = 0; nt < 2; nt++) {
        bias[nt][0] = b_lif[NH + nb + nt * 8 + tig * 2];
        bias[nt][1] = b_lif[NH + nb + nt * 8 + tig * 2 + 1];
    }

    // layer-0 state: thread owns (hp, 8 consecutive b)
    const int hp = tid & (NH - 1);
    const int bh = (tid >> 7) * 8;
    float v0[8];
#pragma unroll
    for (int j = 0; j < 8; j++) v0[j] = 0.f;

    // layer-1 state in C-fragment layout
    float v1[2][4], accr[2][4];
#pragma unroll
    for (int nt = 0; nt < 2; nt++)
#pragma unroll
        for (int r = 0; r < 4; r++) { v1[nt][r] = 0.f; accr[nt][r] = 0.f; }

    // ldmatrix lane addresses for both parity buffers
    const int arow = lane & 15;
    const int acol = (lane >= 16) ? 8 : 0;
    const uint32_t abase0 =
        (uint32_t)__cvta_generic_to_shared(s0s + arow * SROW + acol);
    const uint32_t abase1 = abase0 + MB * SROW * 2;

    __syncthreads();

    // =================== time loop ===================
    for (int t = 0; t < NT; t++) {
        const int p = t & 1;
        unsigned short* sbuf = s0s + p * (MB * SROW);

        // ---- layer 0: membrane update + spike -> s0 tile (bf16 {0,1}) ----
#pragma unroll
        for (int j = 0; j < 8; j++) {
            int b = bh + j;
            int id = idss[b * NT + t];
            float q = Qs[id * NH + hp];
            float v = 0.8f * v0[j] + 0.2f * q;
            bool s = (v >= 1.0f);
            v0[j] = s ? 0.f : v;
            sbuf[b * SROW + hp] = s ? (unsigned short)0x3F80 : (unsigned short)0;
        }
        __syncthreads();  // sole barrier: s0(t) visible before ldmatrix(t)

        // ---- layer 1 drive: 4 independent accumulator chains ----
        float chi[2][4], clo[2][4];
#pragma unroll
        for (int nt = 0; nt < 2; nt++)
#pragma unroll
            for (int r = 0; r < 4; r++) { chi[nt][r] = 0.f; clo[nt][r] = 0.f; }

        const uint32_t ab = p ? abase1 : abase0;
#pragma unroll
        for (int kt = 0; kt < 8; kt++) {
            uint32_t a0, a1, a2, a3;
            uint32_t ad = ab + kt * 32;  // 16 bf16 = 32B per k-tile
            asm volatile(
                "ldmatrix.sync.aligned.m8n8.x4.shared.b16 {%0,%1,%2,%3},[%4];"
                : "=r"(a0), "=r"(a1), "=r"(a2), "=r"(a3)
                : "r"(ad));
            // chain order: chi0, chi1, clo0, clo1 -> same-chain distance 4
            mma_bf16(chi[0], a0, a1, a2, a3, Bhi[kt][0][0], Bhi[kt][0][1]);
            mma_bf16(chi[1], a0, a1, a2, a3, Bhi[kt][1][0], Bhi[kt][1][1]);
            mma_bf16(clo[0], a0, a1, a2, a3, Blo[kt][0][0], Blo[kt][0][1]);
            mma_bf16(clo[1], a0, a1, a2, a3, Blo[kt][1][0], Blo[kt][1][1]);
        }

        // ---- layer-1 membrane/spike/reset + spike accumulation ----
#pragma unroll
        for (int nt = 0; nt < 2; nt++)
#pragma unroll
            for (int r = 0; r < 4; r++) {
                float cur = chi[nt][r] + clo[nt][r] + bias[nt][r & 1];
                float vv = 0.8f * v1[nt][r] + 0.2f * cur;
                bool s = (vv >= 1.0f);
                accr[nt][r] += s ? 1.f : 0.f;
                v1[nt][r] = s ? 0.f : vv;
            }
    }

    // =================== epilogue: classifier ===================
#pragma unroll
    for (int nt = 0; nt < 2; nt++)
#pragma unroll
        for (int r = 0; r < 4; r++) {
            int bl = (r < 2) ? g : (g + 8);
            int col = nb + nt * 8 + tig * 2 + (r & 1);
            accs[bl * NH + col] = accr[nt][r];
        }
    __syncthreads();

    if (tid < MB * NC) {
        int bl = tid / NC;
        int cc = tid % NC;
        float sum = 0.f;
#pragma unroll 8
        for (int h = 0; h < NH; h++) sum += accs[bl * NH + h] * wclss[cc * NH + h];
        out[(b0 + bl) * NC + cc] = sum * (1.0f / NT) + b_cls[cc];
    }
}

// ---------------------------------------------------------------------------
// Host launcher (graph-capturable: kernel launches only)
// Input order: ids, emb, W_in, b_in, W_lif, b_lif, W_rec(unused), W_cls, b_cls
// ---------------------------------------------------------------------------
extern "C" void kernel_launch(void* const* d_in, const int* in_sizes, int n_in,
                              void* d_out, int out_size) {
    const int* ids = (const int*)d_in[0];
    const float* emb = (const float*)d_in[1];
    const float* W_in = (const float*)d_in[2];
    const float* b_in = (const float*)d_in[3];
    const float* W_lif = (const float*)d_in[4];
    const float* b_lif = (const float*)d_in[5];
    const float* W_cls = (const float*)d_in[7];
    const float* b_cls = (const float*)d_in[8];
    float* out = (float*)d_out;

    const int q2_smem = NH * 129 * 4 + 2 * NH * 4;
    cudaFuncSetAttribute(prep_q2_kernel,
                         cudaFuncAttributeMaxDynamicSharedMemorySize, q2_smem);
    cudaFuncSetAttribute(snn_main_kernel,
                         cudaFuncAttributeMaxDynamicSharedMemorySize, SM_BYTES);

    prep_p_kernel<<<NV / 2, 256>>>(emb, W_in, b_in);
    prep_q2_kernel<<<NV / 2, 256, q2_smem>>>(W_lif, b_lif);
    snn_main_kernel<<<NB / MB, 256, SM_BYTES>>>(ids, b_lif, W_cls, b_cls, out);
}